// round 8
// baseline (speedup 1.0000x reference)
#include <cuda_runtime.h>
#include <math.h>

#define NP_MAX     1048576
#define TABLE_SIZE 524288
#define TMASK      (TABLE_SIZE - 1)
#define NUM_LEVELS 8
#define TPB        192
#define W0F        30.0f
#define NSM        148

typedef unsigned long long u64t;

// Encoding scratch, SoA: g_enc[c*N + n], c in [0,32)
__device__ float g_enc[NUM_LEVELS * 4 * NP_MAX];

struct Res8 { float r[8]; };

// ---------------------------------------------------------------------------
// Packed f32x2 helpers (PTX-only; ptxas never auto-fuses FFMA2).
// Two independent .rn fp32 FMAs per instruction -> bit-identical to scalar.
// ---------------------------------------------------------------------------
__device__ __forceinline__ u64t pack2(float x) {
    u64t r; unsigned xi = __float_as_uint(x);
    asm("mov.b64 %0, {%1, %1};" : "=l"(r) : "r"(xi));
    return r;
}
__device__ __forceinline__ u64t packlh(float lo, float hi) {
    u64t r;
    asm("mov.b64 %0, {%1, %2};" : "=l"(r)
        : "r"(__float_as_uint(lo)), "r"(__float_as_uint(hi)));
    return r;
}
__device__ __forceinline__ u64t ffma2(u64t a, u64t b, u64t c) {
    u64t d;
    asm("fma.rn.f32x2 %0, %1, %2, %3;" : "=l"(d) : "l"(a), "l"(b), "l"(c));
    return d;
}
__device__ __forceinline__ float2 unpack2(u64t v) {
    unsigned lo, hi;
    asm("mov.b64 {%0, %1}, %2;" : "=r"(lo), "=r"(hi) : "l"(v));
    return make_float2(__uint_as_float(lo), __uint_as_float(hi));
}

// ---------------------------------------------------------------------------
// Accurate sin, ~1-2 ulp RELATIVE accuracy (SIREN activations contract to
// ~1e-7; MUFU.SIN's absolute error destroys them)
// ---------------------------------------------------------------------------
__device__ __forceinline__ float sin_acc(float x) {
    const float INV_PI = 0.318309886183790672f;
    const float PI_HI  = 3.14159274101257324f;
    const float PI_LO  = -8.74227765734758577e-8f;
    float q = rintf(x * INV_PI);
    float r = fmaf(-q, PI_HI, x);
    r = fmaf(-q, PI_LO, r);
    float r2 = r * r;
    float p = 1.58969104521e-10f;
    p = fmaf(p, r2, -2.50507477726e-8f);
    p = fmaf(p, r2, 2.75573146014e-6f);
    p = fmaf(p, r2, -1.98412701138e-4f);
    p = fmaf(p, r2, 8.33333376795e-3f);
    p = fmaf(p, r2, -1.66666671634e-1f);
    float s = fmaf(p * r2, r, r);
    int qi = (int)q;
    return (qi & 1) ? -s : s;
}

// ---------------------------------------------------------------------------
// Kernel 1: Instant-NGP hash grid encoding
// ---------------------------------------------------------------------------
__global__ void hash_kernel(const float* __restrict__ pts,
                            const float* __restrict__ table,
                            int N, Res8 R) {
    int n = blockIdx.x * blockDim.x + threadIdx.x;
    if (n >= N) return;
    float px = (pts[3 * n + 0] + 1.0f) * 0.5f;
    float py = (pts[3 * n + 1] + 1.0f) * 0.5f;
    float pz = (pts[3 * n + 2] + 1.0f) * 0.5f;
    const float4* tab4 = (const float4*)table;
#pragma unroll
    for (int l = 0; l < NUM_LEVELS; l++) {
        float res = R.r[l];
        float sx = px * res, sy = py * res, sz = pz * res;
        float bx = floorf(sx), by = floorf(sy), bz = floorf(sz);
        float fx = sx - bx, fy = sy - by, fz = sz - bz;
        int ix = (int)bx, iy = (int)by, iz = (int)bz;
        unsigned hx0 = (unsigned)ix;
        unsigned hx1 = (unsigned)(ix + 1);
        unsigned hy0 = (unsigned)iy       * 2654435761u;
        unsigned hy1 = (unsigned)(iy + 1) * 2654435761u;
        unsigned hz0 = (unsigned)iz       * 805459861u;
        unsigned hz1 = (unsigned)(iz + 1) * 805459861u;
        const float4* t = tab4 + (size_t)l * TABLE_SIZE;
        float4 g000 = t[(hx0 ^ hy0 ^ hz0) & TMASK];
        float4 g001 = t[(hx0 ^ hy0 ^ hz1) & TMASK];
        float4 g010 = t[(hx0 ^ hy1 ^ hz0) & TMASK];
        float4 g011 = t[(hx0 ^ hy1 ^ hz1) & TMASK];
        float4 g100 = t[(hx1 ^ hy0 ^ hz0) & TMASK];
        float4 g101 = t[(hx1 ^ hy0 ^ hz1) & TMASK];
        float4 g110 = t[(hx1 ^ hy1 ^ hz0) & TMASK];
        float4 g111 = t[(hx1 ^ hy1 ^ hz1) & TMASK];
        float ux = 1.0f - fx, uy = 1.0f - fy, uz = 1.0f - fz;
        float w000 = ux * uy * uz, w001 = ux * uy * fz;
        float w010 = ux * fy * uz, w011 = ux * fy * fz;
        float w100 = fx * uy * uz, w101 = fx * uy * fz;
        float w110 = fx * fy * uz, w111 = fx * fy * fz;
        float a0 = w000 * g000.x + w001 * g001.x + w010 * g010.x + w011 * g011.x
                 + w100 * g100.x + w101 * g101.x + w110 * g110.x + w111 * g111.x;
        float a1 = w000 * g000.y + w001 * g001.y + w010 * g010.y + w011 * g011.y
                 + w100 * g100.y + w101 * g101.y + w110 * g110.y + w111 * g111.y;
        float a2 = w000 * g000.z + w001 * g001.z + w010 * g010.z + w011 * g011.z
                 + w100 * g100.z + w101 * g101.z + w110 * g110.z + w111 * g111.z;
        float a3 = w000 * g000.w + w001 * g001.w + w010 * g010.w + w011 * g011.w
                 + w100 * g100.w + w101 * g101.w + w110 * g110.w + w111 * g111.w;
        g_enc[(size_t)(l * 4 + 0) * N + n] = a0;
        g_enc[(size_t)(l * 4 + 1) * N + n] = a1;
        g_enc[(size_t)(l * 4 + 2) * N + n] = a2;
        g_enc[(size_t)(l * 4 + 3) * N + n] = a3;
    }
}

// ---------------------------------------------------------------------------
// Kernel 2: fused SIREN MLPs. P=2 points/thread; weights + packed activation
// pairs in SMEM. Weight LDS.128 feeds 4 FFMA2 (2 per point).
// ---------------------------------------------------------------------------
#define O_W1IN  0        // 32*64 = 2048
#define O_B1IN  2048     // 64
#define O_W1H   2112     // 4*64*64 = 16384
#define O_B1H   18496    // 4*64 = 256
#define O_W1OUT 18752    // 64*16 = 1024
#define O_B1OUT 19776    // 16
#define O_W2IN  19792    // 47*64 = 3008
#define O_B2IN  22800    // 64
#define O_W2H   22864    // 2*64*64 = 8192
#define O_B2H   31056    // 2*64 = 128
#define O_W2OUT 31184    // 64
#define O_B2OUT 31248    // 1
#define O_X     31264    // u64 region: 64 cols x TPB packed activation pairs
#define SM_BYTES  (O_X * sizeof(float) + 64 * TPB * sizeof(u64t))

// Hidden layer for 2 points: y = sin(scale*(x @ W + b)), in/out through xb
// (xb[i*TPB+tid] = u64 pair (xA[i], xB[i])). W [IN][64] row-major in SMEM.
template <int IN>
__device__ __forceinline__ void layer_hidden(const float* __restrict__ W,
                                             const float* __restrict__ B,
                                             u64t* __restrict__ xb, int tid,
                                             float scale) {
    u64t accA[32], accB[32];
    const u64t* b2 = (const u64t*)B;
#pragma unroll
    for (int j = 0; j < 32; j++) { accA[j] = b2[j]; accB[j] = b2[j]; }
#pragma unroll 2
    for (int i = 0; i < IN; i++) {
        float2 x2 = unpack2(xb[i * TPB + tid]);
        u64t xa2 = pack2(x2.x);
        u64t xb2 = pack2(x2.y);
        const float4* w4 = (const float4*)(W + i * 64);
#pragma unroll
        for (int q = 0; q < 16; q++) {
            float4 wv = w4[q];
            u64t w01 = packlh(wv.x, wv.y);
            u64t w23 = packlh(wv.z, wv.w);
            accA[2 * q]     = ffma2(xa2, w01, accA[2 * q]);
            accA[2 * q + 1] = ffma2(xa2, w23, accA[2 * q + 1]);
            accB[2 * q]     = ffma2(xb2, w01, accB[2 * q]);
            accB[2 * q + 1] = ffma2(xb2, w23, accB[2 * q + 1]);
        }
    }
#pragma unroll
    for (int j = 0; j < 32; j++) {
        float2 a = unpack2(accA[j]);
        float2 b = unpack2(accB[j]);
        float s0A = sin_acc(scale * a.x), s1A = sin_acc(scale * a.y);
        float s0B = sin_acc(scale * b.x), s1B = sin_acc(scale * b.y);
        xb[(2 * j) * TPB + tid]     = packlh(s0A, s0B);
        xb[(2 * j + 1) * TPB + tid] = packlh(s1A, s1B);
    }
}

// SIREN1 output head: 64 -> 16, no activation, both points.
__device__ __forceinline__ void head16_p2(const float* __restrict__ W,
                                          const float* __restrict__ B,
                                          const u64t* __restrict__ xb, int tid,
                                          float* __restrict__ oA,
                                          float* __restrict__ oB) {
    u64t aA[8], aB[8];
    const u64t* b2 = (const u64t*)B;
#pragma unroll
    for (int j = 0; j < 8; j++) { aA[j] = b2[j]; aB[j] = b2[j]; }
#pragma unroll 2
    for (int i = 0; i < 64; i++) {
        float2 x2 = unpack2(xb[i * TPB + tid]);
        u64t xa2 = pack2(x2.x);
        u64t xb2 = pack2(x2.y);
        const float4* w4 = (const float4*)(W + i * 16);
#pragma unroll
        for (int q = 0; q < 4; q++) {
            float4 wv = w4[q];
            u64t w01 = packlh(wv.x, wv.y);
            u64t w23 = packlh(wv.z, wv.w);
            aA[2 * q]     = ffma2(xa2, w01, aA[2 * q]);
            aA[2 * q + 1] = ffma2(xa2, w23, aA[2 * q + 1]);
            aB[2 * q]     = ffma2(xb2, w01, aB[2 * q]);
            aB[2 * q + 1] = ffma2(xb2, w23, aB[2 * q + 1]);
        }
    }
#pragma unroll
    for (int j = 0; j < 8; j++) {
        float2 a = unpack2(aA[j]); oA[2 * j] = a.x; oA[2 * j + 1] = a.y;
        float2 b = unpack2(aB[j]); oB[2 * j] = b.x; oB[2 * j + 1] = b.y;
    }
}

__global__ void __launch_bounds__(TPB, 1) mlp_kernel(
    const float* __restrict__ s1_win,  const float* __restrict__ s1_bin,
    const float* __restrict__ s1_wh,   const float* __restrict__ s1_bh,
    const float* __restrict__ s1_wout, const float* __restrict__ s1_bout,
    const float* __restrict__ s2_win,  const float* __restrict__ s2_bin,
    const float* __restrict__ s2_wh,   const float* __restrict__ s2_bh,
    const float* __restrict__ s2_wout, const float* __restrict__ s2_bout,
    float* __restrict__ out, int N) {
    extern __shared__ float sm[];
    int tid = threadIdx.x;
#define CPY(off, src, cnt) \
    for (int i = tid; i < (cnt); i += TPB) sm[(off) + i] = (src)[i];
    CPY(O_W1IN,  s1_win,  2048);
    CPY(O_B1IN,  s1_bin,  64);
    CPY(O_W1H,   s1_wh,   16384);
    CPY(O_B1H,   s1_bh,   256);
    CPY(O_W1OUT, s1_wout, 1024);
    CPY(O_B1OUT, s1_bout, 16);
    CPY(O_W2IN,  s2_win,  3008);
    CPY(O_B2IN,  s2_bin,  64);
    CPY(O_W2H,   s2_wh,   8192);
    CPY(O_B2H,   s2_bh,   128);
    CPY(O_W2OUT, s2_wout, 64);
    CPY(O_B2OUT, s2_bout, 1);
#undef CPY
    __syncthreads();

    u64t* xb = (u64t*)(sm + O_X);

    for (int base = blockIdx.x * (2 * TPB); base < N; base += NSM * 2 * TPB) {
        int n0 = base + tid;
        int n1 = base + TPB + tid;
        int n0c = min(n0, N - 1);
        int n1c = min(n1, N - 1);

        // SIREN 1 input: encoding pairs (32 cols)
#pragma unroll
        for (int i = 0; i < 32; i++) {
            float a = g_enc[(size_t)i * N + n0c];
            float b = g_enc[(size_t)i * N + n1c];
            xb[i * TPB + tid] = packlh(a, b);
        }

        layer_hidden<32>(sm + O_W1IN, sm + O_B1IN, xb, tid, W0F);
#pragma unroll
        for (int l = 0; l < 4; l++)
            layer_hidden<64>(sm + O_W1H + l * 4096, sm + O_B1H + l * 64, xb,
                             tid, 1.0f);

        float oA[16], oB[16];
        head16_p2(sm + O_W1OUT, sm + O_B1OUT, xb, tid, oA, oB);
        float dA = fmaxf(oA[0], 0.0f);
        float dB = fmaxf(oB[0], 0.0f);

        // SIREN 2 input: [o[1..15], enc[0..31]] = 47 cols
#pragma unroll
        for (int i = 0; i < 15; i++)
            xb[i * TPB + tid] = packlh(oA[i + 1], oB[i + 1]);
#pragma unroll
        for (int i = 0; i < 32; i++) {
            float a = g_enc[(size_t)i * N + n0c];
            float b = g_enc[(size_t)i * N + n1c];
            xb[(15 + i) * TPB + tid] = packlh(a, b);
        }

        layer_hidden<47>(sm + O_W2IN, sm + O_B2IN, xb, tid, W0F);
#pragma unroll
        for (int l = 0; l < 2; l++)
            layer_hidden<64>(sm + O_W2H + l * 4096, sm + O_B2H + l * 64, xb,
                             tid, 1.0f);

        // SIREN 2 output layer: 64 -> 1, both points
        float scA = sm[O_B2OUT];
        float scB = scA;
        for (int i = 0; i < 64; i++) {
            float2 x2 = unpack2(xb[i * TPB + tid]);
            float w = sm[O_W2OUT + i];
            scA = fmaf(x2.x, w, scA);
            scB = fmaf(x2.y, w, scB);
        }

        if (n0 < N) { out[n0] = scA; out[N + n0] = dA; }
        if (n1 < N) { out[n1] = scB; out[N + n1] = dB; }
    }
}

// ---------------------------------------------------------------------------
extern "C" void kernel_launch(void* const* d_in, const int* in_sizes, int n_in,
                              void* d_out, int out_size) {
    const float* pts     = (const float*)d_in[0];
    const float* table   = (const float*)d_in[1];
    const float* s1_win  = (const float*)d_in[2];
    const float* s1_bin  = (const float*)d_in[3];
    const float* s1_wh   = (const float*)d_in[4];
    const float* s1_bh   = (const float*)d_in[5];
    const float* s1_wout = (const float*)d_in[6];
    const float* s1_bout = (const float*)d_in[7];
    const float* s2_win  = (const float*)d_in[8];
    const float* s2_bin  = (const float*)d_in[9];
    const float* s2_wh   = (const float*)d_in[10];
    const float* s2_bh   = (const float*)d_in[11];
    const float* s2_wout = (const float*)d_in[12];
    const float* s2_bout = (const float*)d_in[13];
    float* out = (float*)d_out;

    int N = in_sizes[0] / 3;

    // Resolutions in host double, EXACTLY mirroring numpy:
    // b = exp((ln 4096 - ln 16)/7); res_l = floor(16 * b**l)
    Res8 R;
    double b = exp((log(4096.0) - log(16.0)) / 7.0);
    for (int l = 0; l < 8; l++) R.r[l] = (float)floor(16.0 * pow(b, (double)l));

    hash_kernel<<<(N + 255) / 256, 256>>>(pts, table, N, R);

    cudaFuncSetAttribute(mlp_kernel, cudaFuncAttributeMaxDynamicSharedMemorySize,
                         (int)SM_BYTES);
    mlp_kernel<<<NSM, TPB, SM_BYTES>>>(s1_win, s1_bin, s1_wh, s1_bh, s1_wout,
                                       s1_bout, s2_win, s2_bin, s2_wh, s2_bh,
                                       s2_wout, s2_bout, out, N);
}

// round 10
// speedup vs baseline: 1.2777x; 1.2777x over previous
#include <cuda_runtime.h>
#include <math.h>

#define NP_MAX     1048576
#define TABLE_SIZE 524288
#define TMASK      (TABLE_SIZE - 1)
#define NUM_LEVELS 8
#define TPB        384
#define W0F        30.0f
#define NSM        148

typedef unsigned long long u64t;

// Encoding scratch, SoA: g_enc[c*N + n], c in [0,32)
__device__ float g_enc[NUM_LEVELS * 4 * NP_MAX];

struct Res8 { float r[8]; };

// ---------------------------------------------------------------------------
// Packed f32x2 helpers (PTX-only; ptxas never auto-fuses FFMA2).
// Two independent .rn fp32 FMAs per instruction -> bit-identical to scalar.
// ---------------------------------------------------------------------------
__device__ __forceinline__ u64t pack2(float x) {
    u64t r; unsigned xi = __float_as_uint(x);
    asm("mov.b64 %0, {%1, %1};" : "=l"(r) : "r"(xi));
    return r;
}
__device__ __forceinline__ u64t packlh(float lo, float hi) {
    u64t r;
    asm("mov.b64 %0, {%1, %2};" : "=l"(r)
        : "r"(__float_as_uint(lo)), "r"(__float_as_uint(hi)));
    return r;
}
__device__ __forceinline__ u64t ffma2(u64t a, u64t b, u64t c) {
    u64t d;
    asm("fma.rn.f32x2 %0, %1, %2, %3;" : "=l"(d) : "l"(a), "l"(b), "l"(c));
    return d;
}
__device__ __forceinline__ float2 unpack2(u64t v) {
    unsigned lo, hi;
    asm("mov.b64 {%0, %1}, %2;" : "=r"(lo), "=r"(hi) : "l"(v));
    return make_float2(__uint_as_float(lo), __uint_as_float(hi));
}

// ---------------------------------------------------------------------------
// Accurate sin, ~1-2 ulp RELATIVE accuracy (SIREN activations contract to
// ~1e-7; MUFU.SIN's absolute error destroys them)
// ---------------------------------------------------------------------------
__device__ __forceinline__ float sin_acc(float x) {
    const float INV_PI = 0.318309886183790672f;
    const float PI_HI  = 3.14159274101257324f;
    const float PI_LO  = -8.74227765734758577e-8f;
    float q = rintf(x * INV_PI);
    float r = fmaf(-q, PI_HI, x);
    r = fmaf(-q, PI_LO, r);
    float r2 = r * r;
    float p = 1.58969104521e-10f;
    p = fmaf(p, r2, -2.50507477726e-8f);
    p = fmaf(p, r2, 2.75573146014e-6f);
    p = fmaf(p, r2, -1.98412701138e-4f);
    p = fmaf(p, r2, 8.33333376795e-3f);
    p = fmaf(p, r2, -1.66666671634e-1f);
    float s = fmaf(p * r2, r, r);
    int qi = (int)q;
    return (qi & 1) ? -s : s;
}

// ---------------------------------------------------------------------------
// Kernel 1: Instant-NGP hash grid encoding
// ---------------------------------------------------------------------------
__global__ void hash_kernel(const float* __restrict__ pts,
                            const float* __restrict__ table,
                            int N, Res8 R) {
    int n = blockIdx.x * blockDim.x + threadIdx.x;
    if (n >= N) return;
    float px = (pts[3 * n + 0] + 1.0f) * 0.5f;
    float py = (pts[3 * n + 1] + 1.0f) * 0.5f;
    float pz = (pts[3 * n + 2] + 1.0f) * 0.5f;
    const float4* tab4 = (const float4*)table;
#pragma unroll
    for (int l = 0; l < NUM_LEVELS; l++) {
        float res = R.r[l];
        float sx = px * res, sy = py * res, sz = pz * res;
        float bx = floorf(sx), by = floorf(sy), bz = floorf(sz);
        float fx = sx - bx, fy = sy - by, fz = sz - bz;
        int ix = (int)bx, iy = (int)by, iz = (int)bz;
        unsigned hx0 = (unsigned)ix;
        unsigned hx1 = (unsigned)(ix + 1);
        unsigned hy0 = (unsigned)iy       * 2654435761u;
        unsigned hy1 = (unsigned)(iy + 1) * 2654435761u;
        unsigned hz0 = (unsigned)iz       * 805459861u;
        unsigned hz1 = (unsigned)(iz + 1) * 805459861u;
        const float4* t = tab4 + (size_t)l * TABLE_SIZE;
        float4 g000 = t[(hx0 ^ hy0 ^ hz0) & TMASK];
        float4 g001 = t[(hx0 ^ hy0 ^ hz1) & TMASK];
        float4 g010 = t[(hx0 ^ hy1 ^ hz0) & TMASK];
        float4 g011 = t[(hx0 ^ hy1 ^ hz1) & TMASK];
        float4 g100 = t[(hx1 ^ hy0 ^ hz0) & TMASK];
        float4 g101 = t[(hx1 ^ hy0 ^ hz1) & TMASK];
        float4 g110 = t[(hx1 ^ hy1 ^ hz0) & TMASK];
        float4 g111 = t[(hx1 ^ hy1 ^ hz1) & TMASK];
        float ux = 1.0f - fx, uy = 1.0f - fy, uz = 1.0f - fz;
        float w000 = ux * uy * uz, w001 = ux * uy * fz;
        float w010 = ux * fy * uz, w011 = ux * fy * fz;
        float w100 = fx * uy * uz, w101 = fx * uy * fz;
        float w110 = fx * fy * uz, w111 = fx * fy * fz;
        float a0 = w000 * g000.x + w001 * g001.x + w010 * g010.x + w011 * g011.x
                 + w100 * g100.x + w101 * g101.x + w110 * g110.x + w111 * g111.x;
        float a1 = w000 * g000.y + w001 * g001.y + w010 * g010.y + w011 * g011.y
                 + w100 * g100.y + w101 * g101.y + w110 * g110.y + w111 * g111.y;
        float a2 = w000 * g000.z + w001 * g001.z + w010 * g010.z + w011 * g011.z
                 + w100 * g100.z + w101 * g101.z + w110 * g110.z + w111 * g111.z;
        float a3 = w000 * g000.w + w001 * g001.w + w010 * g010.w + w011 * g011.w
                 + w100 * g100.w + w101 * g101.w + w110 * g110.w + w111 * g111.w;
        g_enc[(size_t)(l * 4 + 0) * N + n] = a0;
        g_enc[(size_t)(l * 4 + 1) * N + n] = a1;
        g_enc[(size_t)(l * 4 + 2) * N + n] = a2;
        g_enc[(size_t)(l * 4 + 3) * N + n] = a3;
    }
}

// ---------------------------------------------------------------------------
// Kernel 2: fused SIREN MLPs, weights + per-thread activations in SMEM.
// TPB=384 (12 warps). Each 64-out layer computed as two 32-out halves so only
// 16 u64 accumulators are live -> regs fit the 170/thread budget.
// ---------------------------------------------------------------------------
#define O_W1IN  0        // 32*64 = 2048
#define O_B1IN  2048     // 64
#define O_W1H   2112     // 4*64*64 = 16384
#define O_B1H   18496    // 4*64 = 256
#define O_W1OUT 18752    // 64*16 = 1024
#define O_B1OUT 19776    // 16
#define O_W2IN  19792    // 47*64 = 3008
#define O_B2IN  22800    // 64
#define O_W2H   22864    // 2*64*64 = 8192
#define O_B2H   31056    // 2*64 = 128
#define O_W2OUT 31184    // 64
#define O_B2OUT 31248    // 1
#define O_X     31264    // 64*TPB activation columns (scalar float)
#define SM_FLOATS (O_X + 64 * TPB)
#define SM_BYTES  (SM_FLOATS * sizeof(float))

// One 32-output half: acc over all IN inputs, outputs via sin into dst regs.
template <int IN>
__device__ __forceinline__ void half32(const float* __restrict__ W,  // + col offset
                                       const float* __restrict__ B,  // + col offset
                                       const float* __restrict__ xb, int tid,
                                       float scale, u64t* __restrict__ res) {
    u64t acc[16];
    const u64t* b2 = (const u64t*)B;
#pragma unroll
    for (int j = 0; j < 16; j++) acc[j] = b2[j];
#pragma unroll 2
    for (int i = 0; i < IN; i++) {
        u64t xi2 = pack2(xb[i * TPB + tid]);
        const float4* w4 = (const float4*)(W + i * 64);
#pragma unroll
        for (int q = 0; q < 8; q++) {
            float4 wv = w4[q];
            acc[2 * q]     = ffma2(xi2, packlh(wv.x, wv.y), acc[2 * q]);
            acc[2 * q + 1] = ffma2(xi2, packlh(wv.z, wv.w), acc[2 * q + 1]);
        }
    }
#pragma unroll
    for (int j = 0; j < 16; j++) {
        float2 v = unpack2(acc[j]);
        res[j] = packlh(sin_acc(scale * v.x), sin_acc(scale * v.y));
    }
}

// Full hidden layer in-place on xb: two halves; half0 staged in regs until
// all inputs consumed by half1.
template <int IN>
__device__ __forceinline__ void layer64(const float* __restrict__ W,
                                        const float* __restrict__ B,
                                        float* __restrict__ xb, int tid,
                                        float scale) {
    u64t h0[16], h1[16];
    half32<IN>(W,      B,      xb, tid, scale, h0);
    half32<IN>(W + 32, B + 32, xb, tid, scale, h1);
#pragma unroll
    for (int j = 0; j < 16; j++) {
        float2 s = unpack2(h0[j]);
        xb[(2 * j + 0) * TPB + tid] = s.x;
        xb[(2 * j + 1) * TPB + tid] = s.y;
    }
#pragma unroll
    for (int j = 0; j < 16; j++) {
        float2 s = unpack2(h1[j]);
        xb[(32 + 2 * j + 0) * TPB + tid] = s.x;
        xb[(32 + 2 * j + 1) * TPB + tid] = s.y;
    }
}

__global__ void __launch_bounds__(TPB, 1) mlp_kernel(
    const float* __restrict__ s1_win,  const float* __restrict__ s1_bin,
    const float* __restrict__ s1_wh,   const float* __restrict__ s1_bh,
    const float* __restrict__ s1_wout, const float* __restrict__ s1_bout,
    const float* __restrict__ s2_win,  const float* __restrict__ s2_bin,
    const float* __restrict__ s2_wh,   const float* __restrict__ s2_bh,
    const float* __restrict__ s2_wout, const float* __restrict__ s2_bout,
    float* __restrict__ out, int N) {
    extern __shared__ float sm[];
    int tid = threadIdx.x;
#define CPY(off, src, cnt) \
    for (int i = tid; i < (cnt); i += TPB) sm[(off) + i] = (src)[i];
    CPY(O_W1IN,  s1_win,  2048);
    CPY(O_B1IN,  s1_bin,  64);
    CPY(O_W1H,   s1_wh,   16384);
    CPY(O_B1H,   s1_bh,   256);
    CPY(O_W1OUT, s1_wout, 1024);
    CPY(O_B1OUT, s1_bout, 16);
    CPY(O_W2IN,  s2_win,  3008);
    CPY(O_B2IN,  s2_bin,  64);
    CPY(O_W2H,   s2_wh,   8192);
    CPY(O_B2H,   s2_bh,   128);
    CPY(O_W2OUT, s2_wout, 64);
    CPY(O_B2OUT, s2_bout, 1);
#undef CPY
    __syncthreads();

    float* xb = sm + O_X;
    for (int n = blockIdx.x * TPB + tid; n < N; n += NSM * TPB) {
        // SIREN 1 input: encoding (32 cols)
#pragma unroll
        for (int i = 0; i < 32; i++) xb[i * TPB + tid] = g_enc[(size_t)i * N + n];

        layer64<32>(sm + O_W1IN, sm + O_B1IN, xb, tid, W0F);
#pragma unroll
        for (int l = 0; l < 4; l++)
            layer64<64>(sm + O_W1H + l * 4096, sm + O_B1H + l * 64, xb, tid, 1.0f);

        // SIREN 1 output layer: 64 -> 16, no activation
        u64t a16[8];
        {
            const u64t* b2 = (const u64t*)(sm + O_B1OUT);
#pragma unroll
            for (int j = 0; j < 8; j++) a16[j] = b2[j];
#pragma unroll 2
            for (int i = 0; i < 64; i++) {
                u64t xi2 = pack2(xb[i * TPB + tid]);
                const float4* w4 = (const float4*)(sm + O_W1OUT + i * 16);
#pragma unroll
                for (int q = 0; q < 4; q++) {
                    float4 wv = w4[q];
                    a16[2 * q]     = ffma2(xi2, packlh(wv.x, wv.y), a16[2 * q]);
                    a16[2 * q + 1] = ffma2(xi2, packlh(wv.z, wv.w), a16[2 * q + 1]);
                }
            }
        }
        float o[16];
#pragma unroll
        for (int j = 0; j < 8; j++) {
            float2 v = unpack2(a16[j]);
            o[2 * j] = v.x; o[2 * j + 1] = v.y;
        }
        float density = fmaxf(o[0], 0.0f);

        // SIREN 2 input: [o[1..15], enc[0..31]] = 47 cols
#pragma unroll
        for (int i = 0; i < 15; i++) xb[i * TPB + tid] = o[i + 1];
#pragma unroll
        for (int i = 0; i < 32; i++)
            xb[(15 + i) * TPB + tid] = g_enc[(size_t)i * N + n];

        layer64<47>(sm + O_W2IN, sm + O_B2IN, xb, tid, W0F);
#pragma unroll
        for (int l = 0; l < 2; l++)
            layer64<64>(sm + O_W2H + l * 4096, sm + O_B2H + l * 64, xb, tid, 1.0f);

        // SIREN 2 output layer: 64 -> 1
        float sc = sm[O_B2OUT];
        for (int i = 0; i < 64; i++) sc = fmaf(xb[i * TPB + tid], sm[O_W2OUT + i], sc);

        out[n] = sc;          // scalar
        out[N + n] = density; // density
    }
}

// ---------------------------------------------------------------------------
extern "C" void kernel_launch(void* const* d_in, const int* in_sizes, int n_in,
                              void* d_out, int out_size) {
    const float* pts     = (const float*)d_in[0];
    const float* table   = (const float*)d_in[1];
    const float* s1_win  = (const float*)d_in[2];
    const float* s1_bin  = (const float*)d_in[3];
    const float* s1_wh   = (const float*)d_in[4];
    const float* s1_bh   = (const float*)d_in[5];
    const float* s1_wout = (const float*)d_in[6];
    const float* s1_bout = (const float*)d_in[7];
    const float* s2_win  = (const float*)d_in[8];
    const float* s2_bin  = (const float*)d_in[9];
    const float* s2_wh   = (const float*)d_in[10];
    const float* s2_bh   = (const float*)d_in[11];
    const float* s2_wout = (const float*)d_in[12];
    const float* s2_bout = (const float*)d_in[13];
    float* out = (float*)d_out;

    int N = in_sizes[0] / 3;

    // Resolutions in host double, EXACTLY mirroring numpy:
    // b = exp((ln 4096 - ln 16)/7); res_l = floor(16 * b**l)
    Res8 R;
    double b = exp((log(4096.0) - log(16.0)) / 7.0);
    for (int l = 0; l < 8; l++) R.r[l] = (float)floor(16.0 * pow(b, (double)l));

    hash_kernel<<<(N + 255) / 256, 256>>>(pts, table, N, R);

    cudaFuncSetAttribute(mlp_kernel, cudaFuncAttributeMaxDynamicSharedMemorySize,
                         (int)SM_BYTES);
    mlp_kernel<<<NSM, TPB, SM_BYTES>>>(s1_win, s1_bin, s1_wh, s1_bh, s1_wout,
                                       s1_bout, s2_win, s2_bin, s2_wh, s2_bh,
                                       s2_wout, s2_bout, out, N);
}

// round 11
// speedup vs baseline: 1.8057x; 1.4132x over previous
#include <cuda_runtime.h>
#include <math.h>

#define NP_MAX     1048576
#define TABLE_SIZE 524288
#define TMASK      (TABLE_SIZE - 1)
#define NUM_LEVELS 8
#define TPB        384
#define WARPS      (TPB / 32)
#define W0F        30.0f
#define NSM        148
#define XS_STRIDE  68   // 64 + 4 pad floats: 17 16B-chunks (odd) => conflict-free

typedef unsigned long long u64t;

// Encoding scratch, SoA: g_enc[c*N + n], c in [0,32)
__device__ float g_enc[NUM_LEVELS * 4 * NP_MAX];

struct Res8 { float r[8]; };

// ---------------------------------------------------------------------------
// Packed f32x2 helpers (PTX-only; ptxas never auto-fuses FFMA2).
// ---------------------------------------------------------------------------
__device__ __forceinline__ u64t pack2(float x) {
    u64t r; unsigned xi = __float_as_uint(x);
    asm("mov.b64 %0, {%1, %1};" : "=l"(r) : "r"(xi));
    return r;
}
__device__ __forceinline__ u64t ffma2(u64t a, u64t b, u64t c) {
    u64t d;
    asm("fma.rn.f32x2 %0, %1, %2, %3;" : "=l"(d) : "l"(a), "l"(b), "l"(c));
    return d;
}
__device__ __forceinline__ float2 unpack2(u64t v) {
    unsigned lo, hi;
    asm("mov.b64 {%0, %1}, %2;" : "=r"(lo), "=r"(hi) : "l"(v));
    return make_float2(__uint_as_float(lo), __uint_as_float(hi));
}

// ---------------------------------------------------------------------------
// Accurate sin, ~1-2 ulp RELATIVE accuracy (SIREN activations contract to
// ~1e-7; MUFU.SIN's absolute error destroys them)
// ---------------------------------------------------------------------------
__device__ __forceinline__ float sin_acc(float x) {
    const float INV_PI = 0.318309886183790672f;
    const float PI_HI  = 3.14159274101257324f;
    const float PI_LO  = -8.74227765734758577e-8f;
    float q = rintf(x * INV_PI);
    float r = fmaf(-q, PI_HI, x);
    r = fmaf(-q, PI_LO, r);
    float r2 = r * r;
    float p = 1.58969104521e-10f;
    p = fmaf(p, r2, -2.50507477726e-8f);
    p = fmaf(p, r2, 2.75573146014e-6f);
    p = fmaf(p, r2, -1.98412701138e-4f);
    p = fmaf(p, r2, 8.33333376795e-3f);
    p = fmaf(p, r2, -1.66666671634e-1f);
    float s = fmaf(p * r2, r, r);
    int qi = (int)q;
    return (qi & 1) ? -s : s;
}

// ---------------------------------------------------------------------------
// Kernel 1: Instant-NGP hash grid encoding
// ---------------------------------------------------------------------------
__global__ void hash_kernel(const float* __restrict__ pts,
                            const float* __restrict__ table,
                            int N, Res8 R) {
    int n = blockIdx.x * blockDim.x + threadIdx.x;
    if (n >= N) return;
    float px = (pts[3 * n + 0] + 1.0f) * 0.5f;
    float py = (pts[3 * n + 1] + 1.0f) * 0.5f;
    float pz = (pts[3 * n + 2] + 1.0f) * 0.5f;
    const float4* tab4 = (const float4*)table;
#pragma unroll
    for (int l = 0; l < NUM_LEVELS; l++) {
        float res = R.r[l];
        float sx = px * res, sy = py * res, sz = pz * res;
        float bx = floorf(sx), by = floorf(sy), bz = floorf(sz);
        float fx = sx - bx, fy = sy - by, fz = sz - bz;
        int ix = (int)bx, iy = (int)by, iz = (int)bz;
        unsigned hx0 = (unsigned)ix;
        unsigned hx1 = (unsigned)(ix + 1);
        unsigned hy0 = (unsigned)iy       * 2654435761u;
        unsigned hy1 = (unsigned)(iy + 1) * 2654435761u;
        unsigned hz0 = (unsigned)iz       * 805459861u;
        unsigned hz1 = (unsigned)(iz + 1) * 805459861u;
        const float4* t = tab4 + (size_t)l * TABLE_SIZE;
        float4 g000 = t[(hx0 ^ hy0 ^ hz0) & TMASK];
        float4 g001 = t[(hx0 ^ hy0 ^ hz1) & TMASK];
        float4 g010 = t[(hx0 ^ hy1 ^ hz0) & TMASK];
        float4 g011 = t[(hx0 ^ hy1 ^ hz1) & TMASK];
        float4 g100 = t[(hx1 ^ hy0 ^ hz0) & TMASK];
        float4 g101 = t[(hx1 ^ hy0 ^ hz1) & TMASK];
        float4 g110 = t[(hx1 ^ hy1 ^ hz0) & TMASK];
        float4 g111 = t[(hx1 ^ hy1 ^ hz1) & TMASK];
        float ux = 1.0f - fx, uy = 1.0f - fy, uz = 1.0f - fz;
        float w000 = ux * uy * uz, w001 = ux * uy * fz;
        float w010 = ux * fy * uz, w011 = ux * fy * fz;
        float w100 = fx * uy * uz, w101 = fx * uy * fz;
        float w110 = fx * fy * uz, w111 = fx * fy * fz;
        float a0 = w000 * g000.x + w001 * g001.x + w010 * g010.x + w011 * g011.x
                 + w100 * g100.x + w101 * g101.x + w110 * g110.x + w111 * g111.x;
        float a1 = w000 * g000.y + w001 * g001.y + w010 * g010.y + w011 * g011.y
                 + w100 * g100.y + w101 * g101.y + w110 * g110.y + w111 * g111.y;
        float a2 = w000 * g000.z + w001 * g001.z + w010 * g010.z + w011 * g011.z
                 + w100 * g100.z + w101 * g101.z + w110 * g110.z + w111 * g111.z;
        float a3 = w000 * g000.w + w001 * g001.w + w010 * g010.w + w011 * g011.w
                 + w100 * g100.w + w101 * g101.w + w110 * g110.w + w111 * g111.w;
        g_enc[(size_t)(l * 4 + 0) * N + n] = a0;
        g_enc[(size_t)(l * 4 + 1) * N + n] = a1;
        g_enc[(size_t)(l * 4 + 2) * N + n] = a2;
        g_enc[(size_t)(l * 4 + 3) * N + n] = a3;
    }
}

// ---------------------------------------------------------------------------
// Kernel 2: fused SIREN MLPs, warp-tiled. Warp = 32 points x 64 outputs.
// Lane (pg, jg): points {pg, pg+8, pg+16, pg+24}, outputs [16*jg, 16*jg+16).
// ---------------------------------------------------------------------------
#define O_W1IN  0        // 32*64 = 2048
#define O_B1IN  2048     // 64
#define O_W1H   2112     // 4*64*64 = 16384
#define O_B1H   18496    // 4*64 = 256
#define O_W1OUT 18752    // 64*16 = 1024
#define O_B1OUT 19776    // 16
#define O_W2IN  19792    // 48*64 = 3072 (row 47 zero-padded)
#define O_B2IN  22864    // 64
#define O_W2H   22928    // 2*64*64 = 8192
#define O_B2H   31120    // 2*64 = 128
#define O_W2OUT 31248    // 64
#define O_B2OUT 31312    // 1 (+3 pad)
#define O_XS    31316    // 12 warps * 32 points * XS_STRIDE floats
#define SM_FLOATS (O_XS + WARPS * 32 * XS_STRIDE)
#define SM_BYTES  (SM_FLOATS * sizeof(float))

// Hidden layer: y = sin(scale*(x @ W + b)) on the warp tile. IN4 = IN/4.
template <int IN4>
__device__ __forceinline__ void layer_tiled(const float* __restrict__ W,
                                            const float* __restrict__ B,
                                            float* __restrict__ xs,
                                            int pg, int jg, float scale) {
    u64t acc[4][8];
    {
        const ulonglong2* bb = (const ulonglong2*)(B + 16 * jg);
#pragma unroll
        for (int m = 0; m < 4; m++) {
            ulonglong2 b = bb[m];
#pragma unroll
            for (int k = 0; k < 4; k++) {
                acc[k][2 * m]     = b.x;
                acc[k][2 * m + 1] = b.y;
            }
        }
    }
    const float* wbase = W + 16 * jg;
    const float* x0p = xs + pg * XS_STRIDE;
#pragma unroll 2
    for (int i4 = 0; i4 < IN4; i4++) {
        float4 xv[4];
#pragma unroll
        for (int k = 0; k < 4; k++)
            xv[k] = *(const float4*)(x0p + k * 8 * XS_STRIDE + 4 * i4);
#pragma unroll
        for (int ii = 0; ii < 4; ii++) {
            const ulonglong2* wp = (const ulonglong2*)(wbase + (4 * i4 + ii) * 64);
            ulonglong2 wA = wp[0], wB = wp[1], wC = wp[2], wD = wp[3];
#pragma unroll
            for (int k = 0; k < 4; k++) {
                u64t x2 = pack2(((const float*)&xv[k])[ii]);
                acc[k][0] = ffma2(x2, wA.x, acc[k][0]);
                acc[k][1] = ffma2(x2, wA.y, acc[k][1]);
                acc[k][2] = ffma2(x2, wB.x, acc[k][2]);
                acc[k][3] = ffma2(x2, wB.y, acc[k][3]);
                acc[k][4] = ffma2(x2, wC.x, acc[k][4]);
                acc[k][5] = ffma2(x2, wC.y, acc[k][5]);
                acc[k][6] = ffma2(x2, wD.x, acc[k][6]);
                acc[k][7] = ffma2(x2, wD.y, acc[k][7]);
            }
        }
    }
    __syncwarp();
#pragma unroll
    for (int k = 0; k < 4; k++) {
        float* row = xs + (pg + 8 * k) * XS_STRIDE + 16 * jg;
#pragma unroll
        for (int m = 0; m < 4; m++) {
            float2 v0 = unpack2(acc[k][2 * m]);
            float2 v1 = unpack2(acc[k][2 * m + 1]);
            float4 r;
            r.x = sin_acc(scale * v0.x);
            r.y = sin_acc(scale * v0.y);
            r.z = sin_acc(scale * v1.x);
            r.w = sin_acc(scale * v1.y);
            *(float4*)(row + 4 * m) = r;
        }
    }
    __syncwarp();
}

// SIREN1 head: 64 -> 16, no activation. Lane owns outputs [4jg, 4jg+4).
__device__ __forceinline__ void head16_tiled(const float* __restrict__ W,
                                             const float* __restrict__ B,
                                             const float* __restrict__ xs,
                                             int pg, int jg, float o[4][4]) {
    u64t acc[4][2];
    {
        const ulonglong2* bb = (const ulonglong2*)(B + 4 * jg);
        ulonglong2 b = bb[0];
#pragma unroll
        for (int k = 0; k < 4; k++) { acc[k][0] = b.x; acc[k][1] = b.y; }
    }
    const float* x0p = xs + pg * XS_STRIDE;
#pragma unroll 2
    for (int i4 = 0; i4 < 16; i4++) {
        float4 xv[4];
#pragma unroll
        for (int k = 0; k < 4; k++)
            xv[k] = *(const float4*)(x0p + k * 8 * XS_STRIDE + 4 * i4);
#pragma unroll
        for (int ii = 0; ii < 4; ii++) {
            const ulonglong2* wp = (const ulonglong2*)(W + (4 * i4 + ii) * 16 + 4 * jg);
            ulonglong2 w = wp[0];
#pragma unroll
            for (int k = 0; k < 4; k++) {
                u64t x2 = pack2(((const float*)&xv[k])[ii]);
                acc[k][0] = ffma2(x2, w.x, acc[k][0]);
                acc[k][1] = ffma2(x2, w.y, acc[k][1]);
            }
        }
    }
#pragma unroll
    for (int k = 0; k < 4; k++) {
        float2 v0 = unpack2(acc[k][0]);
        float2 v1 = unpack2(acc[k][1]);
        o[k][0] = v0.x; o[k][1] = v0.y; o[k][2] = v1.x; o[k][3] = v1.y;
    }
}

__global__ void __launch_bounds__(TPB, 1) mlp_kernel(
    const float* __restrict__ s1_win,  const float* __restrict__ s1_bin,
    const float* __restrict__ s1_wh,   const float* __restrict__ s1_bh,
    const float* __restrict__ s1_wout, const float* __restrict__ s1_bout,
    const float* __restrict__ s2_win,  const float* __restrict__ s2_bin,
    const float* __restrict__ s2_wh,   const float* __restrict__ s2_bh,
    const float* __restrict__ s2_wout, const float* __restrict__ s2_bout,
    float* __restrict__ out, int N) {
    extern __shared__ float sm[];
    int tid = threadIdx.x;
#define CPY(off, src, cnt) \
    for (int i = tid; i < (cnt); i += TPB) sm[(off) + i] = (src)[i];
    CPY(O_W1IN,  s1_win,  2048);
    CPY(O_B1IN,  s1_bin,  64);
    CPY(O_W1H,   s1_wh,   16384);
    CPY(O_B1H,   s1_bh,   256);
    CPY(O_W1OUT, s1_wout, 1024);
    CPY(O_B1OUT, s1_bout, 16);
    CPY(O_W2IN,  s2_win,  3008);
    CPY(O_B2IN,  s2_bin,  64);
    CPY(O_W2H,   s2_wh,   8192);
    CPY(O_B2H,   s2_bh,   128);
    CPY(O_W2OUT, s2_wout, 64);
    CPY(O_B2OUT, s2_bout, 1);
#undef CPY
    // zero-pad W2in row 47 (x[47] is also forced to 0 each pass)
    for (int i = tid; i < 64; i += TPB) sm[O_W2IN + 47 * 64 + i] = 0.0f;
    __syncthreads();

    int wid  = tid >> 5;
    int lane = tid & 31;
    int pg = lane & 7;
    int jg = lane >> 3;
    float* xs = sm + O_XS + wid * (32 * XS_STRIDE);

    int ntiles = (N + 31) >> 5;
    for (int t = blockIdx.x * WARPS + wid; t < ntiles; t += NSM * WARPS) {
        int nb = t << 5;

        // SIREN 1 inputs: row lane = point nb+lane, cols 0..31 = enc
        {
            int nl = min(nb + lane, N - 1);
            float* row = xs + lane * XS_STRIDE;
#pragma unroll
            for (int c = 0; c < 32; c++) row[c] = g_enc[(size_t)c * N + nl];
        }
        __syncwarp();

        layer_tiled<8>(sm + O_W1IN, sm + O_B1IN, xs, pg, jg, W0F);
#pragma unroll
        for (int l = 0; l < 4; l++)
            layer_tiled<16>(sm + O_W1H + l * 4096, sm + O_B1H + l * 64, xs,
                            pg, jg, 1.0f);

        float o[4][4];
        head16_tiled(sm + O_W1OUT, sm + O_B1OUT, xs, pg, jg, o);

        float dens[4];
#pragma unroll
        for (int k = 0; k < 4; k++) dens[k] = fmaxf(o[k][0], 0.0f);

        __syncwarp();
        // SIREN 2 inputs: cols 0..14 = o[1..15], cols 15..46 = enc, col 47 = 0
#pragma unroll
        for (int k = 0; k < 4; k++) {
            float* row = xs + (pg + 8 * k) * XS_STRIDE;
#pragma unroll
            for (int c = 0; c < 4; c++) {
                int j = 4 * jg + c;
                if (j >= 1) row[j - 1] = o[k][c];
            }
        }
        {
            int nl = min(nb + lane, N - 1);
            float* row = xs + lane * XS_STRIDE;
#pragma unroll
            for (int c = 0; c < 32; c++) row[15 + c] = g_enc[(size_t)c * N + nl];
            row[47] = 0.0f;
        }
        __syncwarp();

        layer_tiled<12>(sm + O_W2IN, sm + O_B2IN, xs, pg, jg, W0F);
#pragma unroll
        for (int l = 0; l < 2; l++)
            layer_tiled<16>(sm + O_W2H + l * 4096, sm + O_B2H + l * 64, xs,
                            pg, jg, 1.0f);

        // SIREN 2 output layer: 64 -> 1 (lane sums i in [16jg,16jg+16), then
        // butterfly-reduce across the 4 jg lanes)
        float part[4] = {0.0f, 0.0f, 0.0f, 0.0f};
        const float* wv  = sm + O_W2OUT + 16 * jg;
        const float* x0p = xs + pg * XS_STRIDE + 16 * jg;
#pragma unroll
        for (int q = 0; q < 4; q++) {
            float4 w = *(const float4*)(wv + 4 * q);
#pragma unroll
            for (int k = 0; k < 4; k++) {
                float4 x = *(const float4*)(x0p + k * 8 * XS_STRIDE + 4 * q);
                part[k] = fmaf(x.x, w.x, part[k]);
                part[k] = fmaf(x.y, w.y, part[k]);
                part[k] = fmaf(x.z, w.z, part[k]);
                part[k] = fmaf(x.w, w.w, part[k]);
            }
        }
#pragma unroll
        for (int k = 0; k < 4; k++) {
            part[k] += __shfl_xor_sync(0xFFFFFFFF, part[k], 8);
            part[k] += __shfl_xor_sync(0xFFFFFFFF, part[k], 16);
        }
        float b2 = sm[O_B2OUT];
        if (jg == 0) {
#pragma unroll
            for (int k = 0; k < 4; k++) {
                int n = nb + pg + 8 * k;
                if (n < N) { out[n] = part[k] + b2; out[N + n] = dens[k]; }
            }
        }
        __syncwarp();
    }
}

// ---------------------------------------------------------------------------
extern "C" void kernel_launch(void* const* d_in, const int* in_sizes, int n_in,
                              void* d_out, int out_size) {
    const float* pts     = (const float*)d_in[0];
    const float* table   = (const float*)d_in[1];
    const float* s1_win  = (const float*)d_in[2];
    const float* s1_bin  = (const float*)d_in[3];
    const float* s1_wh   = (const float*)d_in[4];
    const float* s1_bh   = (const float*)d_in[5];
    const float* s1_wout = (const float*)d_in[6];
    const float* s1_bout = (const float*)d_in[7];
    const float* s2_win  = (const float*)d_in[8];
    const float* s2_bin  = (const float*)d_in[9];
    const float* s2_wh   = (const float*)d_in[10];
    const float* s2_bh   = (const float*)d_in[11];
    const float* s2_wout = (const float*)d_in[12];
    const float* s2_bout = (const float*)d_in[13];
    float* out = (float*)d_out;

    int N = in_sizes[0] / 3;

    // Resolutions in host double, EXACTLY mirroring numpy:
    // b = exp((ln 4096 - ln 16)/7); res_l = floor(16 * b**l)
    Res8 R;
    double b = exp((log(4096.0) - log(16.0)) / 7.0);
    for (int l = 0; l < 8; l++) R.r[l] = (float)floor(16.0 * pow(b, (double)l));

    hash_kernel<<<(N + 255) / 256, 256>>>(pts, table, N, R);

    cudaFuncSetAttribute(mlp_kernel, cudaFuncAttributeMaxDynamicSharedMemorySize,
                         (int)SM_BYTES);
    mlp_kernel<<<NSM, TPB, SM_BYTES>>>(s1_win, s1_bin, s1_wh, s1_bh, s1_wout,
                                       s1_bout, s2_win, s2_bin, s2_wh, s2_bh,
                                       s2_wout, s2_bout, out, N);
}

// round 15
// speedup vs baseline: 1.8513x; 1.0253x over previous
#include <cuda_runtime.h>
#include <math.h>

#define NP_MAX     1048576
#define TABLE_SIZE 524288
#define TMASK      (TABLE_SIZE - 1)
#define NUM_LEVELS 8
#define W0F        30.0f
#define NSM        148

#define TPB1       512
#define WARPS1     (TPB1 / 32)
#define TPB2       512
#define WARPS2     (TPB2 / 32)
#define XS1        68   // 17 odd 16B-chunks: conflict-free; >= 64 (layer outputs!)
#define XS2        68   // MUST be >= 64: hidden layers write 64 cols back into xs

typedef unsigned long long u64t;

// Encoding scratch, SoA: g_enc[c*N + n], c in [0,32)
__device__ float g_enc[NUM_LEVELS * 4 * NP_MAX];
// siren1 head output (o[0..15]) per point, lane-owned float4 chunks
__device__ float4 g_mid[NP_MAX * 4];

struct Res8 { float r[8]; };

// ---------------------------------------------------------------------------
// Packed f32x2 helpers (PTX-only; ptxas never auto-fuses FFMA2).
// ---------------------------------------------------------------------------
__device__ __forceinline__ u64t pack2(float x) {
    u64t r; unsigned xi = __float_as_uint(x);
    asm("mov.b64 %0, {%1, %1};" : "=l"(r) : "r"(xi));
    return r;
}
__device__ __forceinline__ u64t ffma2(u64t a, u64t b, u64t c) {
    u64t d;
    asm("fma.rn.f32x2 %0, %1, %2, %3;" : "=l"(d) : "l"(a), "l"(b), "l"(c));
    return d;
}
__device__ __forceinline__ float2 unpack2(u64t v) {
    unsigned lo, hi;
    asm("mov.b64 {%0, %1}, %2;" : "=r"(lo), "=r"(hi) : "l"(v));
    return make_float2(__uint_as_float(lo), __uint_as_float(hi));
}

// ---------------------------------------------------------------------------
// Accurate sin, ~1-2 ulp RELATIVE accuracy
// ---------------------------------------------------------------------------
__device__ __forceinline__ float sin_acc(float x) {
    const float INV_PI = 0.318309886183790672f;
    const float PI_HI  = 3.14159274101257324f;
    const float PI_LO  = -8.74227765734758577e-8f;
    float q = rintf(x * INV_PI);
    float r = fmaf(-q, PI_HI, x);
    r = fmaf(-q, PI_LO, r);
    float r2 = r * r;
    float p = 1.58969104521e-10f;
    p = fmaf(p, r2, -2.50507477726e-8f);
    p = fmaf(p, r2, 2.75573146014e-6f);
    p = fmaf(p, r2, -1.98412701138e-4f);
    p = fmaf(p, r2, 8.33333376795e-3f);
    p = fmaf(p, r2, -1.66666671634e-1f);
    float s = fmaf(p * r2, r, r);
    int qi = (int)q;
    return (qi & 1) ? -s : s;
}

// ---------------------------------------------------------------------------
// Kernel 1: Instant-NGP hash grid encoding
// ---------------------------------------------------------------------------
__global__ void hash_kernel(const float* __restrict__ pts,
                            const float* __restrict__ table,
                            int N, Res8 R) {
    int n = blockIdx.x * blockDim.x + threadIdx.x;
    if (n >= N) return;
    float px = (pts[3 * n + 0] + 1.0f) * 0.5f;
    float py = (pts[3 * n + 1] + 1.0f) * 0.5f;
    float pz = (pts[3 * n + 2] + 1.0f) * 0.5f;
    const float4* tab4 = (const float4*)table;
#pragma unroll
    for (int l = 0; l < NUM_LEVELS; l++) {
        float res = R.r[l];
        float sx = px * res, sy = py * res, sz = pz * res;
        float bx = floorf(sx), by = floorf(sy), bz = floorf(sz);
        float fx = sx - bx, fy = sy - by, fz = sz - bz;
        int ix = (int)bx, iy = (int)by, iz = (int)bz;
        unsigned hx0 = (unsigned)ix;
        unsigned hx1 = (unsigned)(ix + 1);
        unsigned hy0 = (unsigned)iy       * 2654435761u;
        unsigned hy1 = (unsigned)(iy + 1) * 2654435761u;
        unsigned hz0 = (unsigned)iz       * 805459861u;
        unsigned hz1 = (unsigned)(iz + 1) * 805459861u;
        const float4* t = tab4 + (size_t)l * TABLE_SIZE;
        float4 g000 = t[(hx0 ^ hy0 ^ hz0) & TMASK];
        float4 g001 = t[(hx0 ^ hy0 ^ hz1) & TMASK];
        float4 g010 = t[(hx0 ^ hy1 ^ hz0) & TMASK];
        float4 g011 = t[(hx0 ^ hy1 ^ hz1) & TMASK];
        float4 g100 = t[(hx1 ^ hy0 ^ hz0) & TMASK];
        float4 g101 = t[(hx1 ^ hy0 ^ hz1) & TMASK];
        float4 g110 = t[(hx1 ^ hy1 ^ hz0) & TMASK];
        float4 g111 = t[(hx1 ^ hy1 ^ hz1) & TMASK];
        float ux = 1.0f - fx, uy = 1.0f - fy, uz = 1.0f - fz;
        float w000 = ux * uy * uz, w001 = ux * uy * fz;
        float w010 = ux * fy * uz, w011 = ux * fy * fz;
        float w100 = fx * uy * uz, w101 = fx * uy * fz;
        float w110 = fx * fy * uz, w111 = fx * fy * fz;
        float a0 = w000 * g000.x + w001 * g001.x + w010 * g010.x + w011 * g011.x
                 + w100 * g100.x + w101 * g101.x + w110 * g110.x + w111 * g111.x;
        float a1 = w000 * g000.y + w001 * g001.y + w010 * g010.y + w011 * g011.y
                 + w100 * g100.y + w101 * g101.y + w110 * g110.y + w111 * g111.y;
        float a2 = w000 * g000.z + w001 * g001.z + w010 * g010.z + w011 * g011.z
                 + w100 * g100.z + w101 * g101.z + w110 * g110.z + w111 * g111.z;
        float a3 = w000 * g000.w + w001 * g001.w + w010 * g010.w + w011 * g011.w
                 + w100 * g100.w + w101 * g101.w + w110 * g110.w + w111 * g111.w;
        g_enc[(size_t)(l * 4 + 0) * N + n] = a0;
        g_enc[(size_t)(l * 4 + 1) * N + n] = a1;
        g_enc[(size_t)(l * 4 + 2) * N + n] = a2;
        g_enc[(size_t)(l * 4 + 3) * N + n] = a3;
    }
}

// ---------------------------------------------------------------------------
// Warp-tiled layer: warp = 32 points x 64 outputs.
// Lane (pg, jg): points {pg, pg+8, pg+16, pg+24}, outputs [16*jg, 16*jg+16).
// ---------------------------------------------------------------------------
template <int IN4, int STRIDE>
__device__ __forceinline__ void layer_tiled(const float* __restrict__ W,
                                            const float* __restrict__ B,
                                            float* __restrict__ xs,
                                            int pg, int jg, float scale) {
    u64t acc[4][8];
    {
        const ulonglong2* bb = (const ulonglong2*)(B + 16 * jg);
#pragma unroll
        for (int m = 0; m < 4; m++) {
            ulonglong2 b = bb[m];
#pragma unroll
            for (int k = 0; k < 4; k++) {
                acc[k][2 * m]     = b.x;
                acc[k][2 * m + 1] = b.y;
            }
        }
    }
    const float* wbase = W + 16 * jg;
    const float* x0p = xs + pg * STRIDE;
#pragma unroll 2
    for (int i4 = 0; i4 < IN4; i4++) {
        float4 xv[4];
#pragma unroll
        for (int k = 0; k < 4; k++)
            xv[k] = *(const float4*)(x0p + k * 8 * STRIDE + 4 * i4);
#pragma unroll
        for (int ii = 0; ii < 4; ii++) {
            const ulonglong2* wp = (const ulonglong2*)(wbase + (4 * i4 + ii) * 64);
            ulonglong2 wA = wp[0], wB = wp[1], wC = wp[2], wD = wp[3];
#pragma unroll
            for (int k = 0; k < 4; k++) {
                u64t x2 = pack2(((const float*)&xv[k])[ii]);
                acc[k][0] = ffma2(x2, wA.x, acc[k][0]);
                acc[k][1] = ffma2(x2, wA.y, acc[k][1]);
                acc[k][2] = ffma2(x2, wB.x, acc[k][2]);
                acc[k][3] = ffma2(x2, wB.y, acc[k][3]);
                acc[k][4] = ffma2(x2, wC.x, acc[k][4]);
                acc[k][5] = ffma2(x2, wC.y, acc[k][5]);
                acc[k][6] = ffma2(x2, wD.x, acc[k][6]);
                acc[k][7] = ffma2(x2, wD.y, acc[k][7]);
            }
        }
    }
    __syncwarp();
#pragma unroll
    for (int k = 0; k < 4; k++) {
        float* row = xs + (pg + 8 * k) * STRIDE + 16 * jg;
#pragma unroll
        for (int m = 0; m < 4; m++) {
            float2 v0 = unpack2(acc[k][2 * m]);
            float2 v1 = unpack2(acc[k][2 * m + 1]);
            float4 r;
            r.x = sin_acc(scale * v0.x);
            r.y = sin_acc(scale * v0.y);
            r.z = sin_acc(scale * v1.x);
            r.w = sin_acc(scale * v1.y);
            *(float4*)(row + 4 * m) = r;
        }
    }
    __syncwarp();
}

// SIREN1 head: 64 -> 16, no activation. Lane owns outputs [4jg, 4jg+4).
template <int STRIDE>
__device__ __forceinline__ void head16_tiled(const float* __restrict__ W,
                                             const float* __restrict__ B,
                                             const float* __restrict__ xs,
                                             int pg, int jg, float o[4][4]) {
    u64t acc[4][2];
    {
        const ulonglong2* bb = (const ulonglong2*)(B + 4 * jg);
        ulonglong2 b = bb[0];
#pragma unroll
        for (int k = 0; k < 4; k++) { acc[k][0] = b.x; acc[k][1] = b.y; }
    }
    const float* x0p = xs + pg * STRIDE;
#pragma unroll 2
    for (int i4 = 0; i4 < 16; i4++) {
        float4 xv[4];
#pragma unroll
        for (int k = 0; k < 4; k++)
            xv[k] = *(const float4*)(x0p + k * 8 * STRIDE + 4 * i4);
#pragma unroll
        for (int ii = 0; ii < 4; ii++) {
            const ulonglong2* wp = (const ulonglong2*)(W + (4 * i4 + ii) * 16 + 4 * jg);
            ulonglong2 w = wp[0];
#pragma unroll
            for (int k = 0; k < 4; k++) {
                u64t x2 = pack2(((const float*)&xv[k])[ii]);
                acc[k][0] = ffma2(x2, w.x, acc[k][0]);
                acc[k][1] = ffma2(x2, w.y, acc[k][1]);
            }
        }
    }
#pragma unroll
    for (int k = 0; k < 4; k++) {
        float2 v0 = unpack2(acc[k][0]);
        float2 v1 = unpack2(acc[k][1]);
        o[k][0] = v0.x; o[k][1] = v0.y; o[k][2] = v1.x; o[k][3] = v1.y;
    }
}

// ---------------------------------------------------------------------------
// Kernel 2: SIREN 1 (enc32 -> 64 -> 4x64 -> head16). Writes g_mid + density.
// ---------------------------------------------------------------------------
#define O1_W1IN  0        // 32*64 = 2048
#define O1_B1IN  2048     // 64
#define O1_W1H   2112     // 4*64*64 = 16384
#define O1_B1H   18496    // 4*64 = 256
#define O1_W1OUT 18752    // 64*16 = 1024
#define O1_B1OUT 19776    // 16
#define O1_XS    19792
#define SM1_BYTES ((O1_XS + WARPS1 * 32 * XS1) * sizeof(float))

__global__ void __launch_bounds__(TPB1, 1) mlp1_kernel(
    const float* __restrict__ s1_win,  const float* __restrict__ s1_bin,
    const float* __restrict__ s1_wh,   const float* __restrict__ s1_bh,
    const float* __restrict__ s1_wout, const float* __restrict__ s1_bout,
    float* __restrict__ out, int N) {
    extern __shared__ float sm[];
    int tid = threadIdx.x;
#define CPY(off, src, cnt) \
    for (int i = tid; i < (cnt); i += TPB1) sm[(off) + i] = (src)[i];
    CPY(O1_W1IN,  s1_win,  2048);
    CPY(O1_B1IN,  s1_bin,  64);
    CPY(O1_W1H,   s1_wh,   16384);
    CPY(O1_B1H,   s1_bh,   256);
    CPY(O1_W1OUT, s1_wout, 1024);
    CPY(O1_B1OUT, s1_bout, 16);
#undef CPY
    __syncthreads();

    int wid  = tid >> 5;
    int lane = tid & 31;
    int pg = lane & 7;
    int jg = lane >> 3;
    float* xs = sm + O1_XS + wid * (32 * XS1);

    int ntiles = (N + 31) >> 5;
    for (int t = blockIdx.x * WARPS1 + wid; t < ntiles; t += NSM * WARPS1) {
        int nb = t << 5;
        {
            int nl = min(nb + lane, N - 1);
            float* row = xs + lane * XS1;
#pragma unroll
            for (int c = 0; c < 32; c++) row[c] = g_enc[(size_t)c * N + nl];
        }
        __syncwarp();

        layer_tiled<8, XS1>(sm + O1_W1IN, sm + O1_B1IN, xs, pg, jg, W0F);
#pragma unroll
        for (int l = 0; l < 4; l++)
            layer_tiled<16, XS1>(sm + O1_W1H + l * 4096, sm + O1_B1H + l * 64,
                                 xs, pg, jg, 1.0f);

        float o[4][4];
        head16_tiled<XS1>(sm + O1_W1OUT, sm + O1_B1OUT, xs, pg, jg, o);

#pragma unroll
        for (int k = 0; k < 4; k++) {
            int n = nb + pg + 8 * k;
            if (n < N) {
                g_mid[(size_t)n * 4 + jg] =
                    make_float4(o[k][0], o[k][1], o[k][2], o[k][3]);
                if (jg == 0) out[N + n] = fmaxf(o[k][0], 0.0f);
            }
        }
        __syncwarp();
    }
}

// ---------------------------------------------------------------------------
// Kernel 3: SIREN 2 ([o1..15, enc32, 0pad] -> 64 -> 2x64 -> 1). Writes scalar.
// ---------------------------------------------------------------------------
#define O2_W2IN  0        // 48*64 = 3072 (row 47 zero-padded)
#define O2_B2IN  3072     // 64
#define O2_W2H   3136     // 2*64*64 = 8192
#define O2_B2H   11328    // 128
#define O2_W2OUT 11456    // 64
#define O2_B2OUT 11520    // 1 (+3 pad)
#define O2_XS    11524
#define SM2_BYTES ((O2_XS + WARPS2 * 32 * XS2) * sizeof(float))

__global__ void __launch_bounds__(TPB2, 1) mlp2_kernel(
    const float* __restrict__ s2_win,  const float* __restrict__ s2_bin,
    const float* __restrict__ s2_wh,   const float* __restrict__ s2_bh,
    const float* __restrict__ s2_wout, const float* __restrict__ s2_bout,
    float* __restrict__ out, int N) {
    extern __shared__ float sm[];
    int tid = threadIdx.x;
#define CPY(off, src, cnt) \
    for (int i = tid; i < (cnt); i += TPB2) sm[(off) + i] = (src)[i];
    CPY(O2_W2IN,  s2_win,  3008);
    CPY(O2_B2IN,  s2_bin,  64);
    CPY(O2_W2H,   s2_wh,   8192);
    CPY(O2_B2H,   s2_bh,   128);
    CPY(O2_W2OUT, s2_wout, 64);
    CPY(O2_B2OUT, s2_bout, 1);
#undef CPY
    for (int i = tid; i < 64; i += TPB2) sm[O2_W2IN + 47 * 64 + i] = 0.0f;
    __syncthreads();

    int wid  = tid >> 5;
    int lane = tid & 31;
    int pg = lane & 7;
    int jg = lane >> 3;
    float* xs = sm + O2_XS + wid * (32 * XS2);

    int ntiles = (N + 31) >> 5;
    for (int t = blockIdx.x * WARPS2 + wid; t < ntiles; t += NSM * WARPS2) {
        int nb = t << 5;

        // cols 0..14: o[1..15] from g_mid (lane reads its own chunk)
#pragma unroll
        for (int k = 0; k < 4; k++) {
            int n = min(nb + pg + 8 * k, N - 1);
            float4 v = g_mid[(size_t)n * 4 + jg];
            float* row = xs + (pg + 8 * k) * XS2;
            float vv[4] = {v.x, v.y, v.z, v.w};
#pragma unroll
            for (int c = 0; c < 4; c++) {
                int j = 4 * jg + c;
                if (j >= 1) row[j - 1] = vv[c];
            }
        }
        // cols 15..46: enc; col 47: 0
        {
            int nl = min(nb + lane, N - 1);
            float* row = xs + lane * XS2;
#pragma unroll
            for (int c = 0; c < 32; c++) row[15 + c] = g_enc[(size_t)c * N + nl];
            row[47] = 0.0f;
        }
        __syncwarp();

        layer_tiled<12, XS2>(sm + O2_W2IN, sm + O2_B2IN, xs, pg, jg, W0F);
#pragma unroll
        for (int l = 0; l < 2; l++)
            layer_tiled<16, XS2>(sm + O2_W2H + l * 4096, sm + O2_B2H + l * 64,
                                 xs, pg, jg, 1.0f);

        // 64 -> 1: lane sums i in [16jg,16jg+16), butterfly across jg lanes
        float part[4] = {0.0f, 0.0f, 0.0f, 0.0f};
        const float* wv  = sm + O2_W2OUT + 16 * jg;
        const float* x0p = xs + pg * XS2 + 16 * jg;
#pragma unroll
        for (int q = 0; q < 4; q++) {
            float4 w = *(const float4*)(wv + 4 * q);
#pragma unroll
            for (int k = 0; k < 4; k++) {
                float4 x = *(const float4*)(x0p + k * 8 * XS2 + 4 * q);
                part[k] = fmaf(x.x, w.x, part[k]);
                part[k] = fmaf(x.y, w.y, part[k]);
                part[k] = fmaf(x.z, w.z, part[k]);
                part[k] = fmaf(x.w, w.w, part[k]);
            }
        }
#pragma unroll
        for (int k = 0; k < 4; k++) {
            part[k] += __shfl_xor_sync(0xFFFFFFFF, part[k], 8);
            part[k] += __shfl_xor_sync(0xFFFFFFFF, part[k], 16);
        }
        float b2 = sm[O2_B2OUT];
        if (jg == 0) {
#pragma unroll
            for (int k = 0; k < 4; k++) {
                int n = nb + pg + 8 * k;
                if (n < N) out[n] = part[k] + b2;
            }
        }
        __syncwarp();
    }
}

// ---------------------------------------------------------------------------
extern "C" void kernel_launch(void* const* d_in, const int* in_sizes, int n_in,
                              void* d_out, int out_size) {
    const float* pts     = (const float*)d_in[0];
    const float* table   = (const float*)d_in[1];
    const float* s1_win  = (const float*)d_in[2];
    const float* s1_bin  = (const float*)d_in[3];
    const float* s1_wh   = (const float*)d_in[4];
    const float* s1_bh   = (const float*)d_in[5];
    const float* s1_wout = (const float*)d_in[6];
    const float* s1_bout = (const float*)d_in[7];
    const float* s2_win  = (const float*)d_in[8];
    const float* s2_bin  = (const float*)d_in[9];
    const float* s2_wh   = (const float*)d_in[10];
    const float* s2_bh   = (const float*)d_in[11];
    const float* s2_wout = (const float*)d_in[12];
    const float* s2_bout = (const float*)d_in[13];
    float* out = (float*)d_out;

    int N = in_sizes[0] / 3;

    // Resolutions in host double, EXACTLY mirroring numpy:
    Res8 R;
    double b = exp((log(4096.0) - log(16.0)) / 7.0);
    for (int l = 0; l < 8; l++) R.r[l] = (float)floor(16.0 * pow(b, (double)l));

    hash_kernel<<<(N + 255) / 256, 256>>>(pts, table, N, R);

    cudaFuncSetAttribute(mlp1_kernel, cudaFuncAttributeMaxDynamicSharedMemorySize,
                         (int)SM1_BYTES);
    cudaFuncSetAttribute(mlp2_kernel, cudaFuncAttributeMaxDynamicSharedMemorySize,
                         (int)SM2_BYTES);
    mlp1_kernel<<<NSM, TPB1, SM1_BYTES>>>(s1_win, s1_bin, s1_wh, s1_bh,
                                          s1_wout, s1_bout, out, N);
    mlp2_kernel<<<NSM, TPB2, SM2_BYTES>>>(s2_win, s2_bin, s2_wh, s2_bh,
                                          s2_wout, s2_bout, out, N);
}